// round 14
// baseline (speedup 1.0000x reference)
#include <cuda_runtime.h>
#include <cuda_bf16.h>

#define D_IN   592
#define NBATCH 8192
#define FB     8
#define NW     4            // warps (samples) per CTA
#define NT     (NW * 32)
#define WSH    512          // floats/warp: p1 444 + p2 36 + h1 20 (+pad)
#define FULLM  0xffffffffu

// Uniform-accessed small weights live in constant memory (LDCU port, off LSU).
// Layout per bank i: [0..8] conv1_w, [9..11] conv1_b, [12..20] conv2_w, [21] conv2_b, [22] lin3_b
#define CPB 23
__constant__ float c_cw[FB * CPB];

__global__ void __launch_bounds__(NT, 8) fbank_kernel(
    const float* __restrict__ x,
    const float* __restrict__ l1w, const float* __restrict__ l1b,
    const float* __restrict__ l2w, const float* __restrict__ l2b,
    const float* __restrict__ l3w,
    float* __restrict__ outH, float* __restrict__ outXF,
    float* __restrict__ outXS, float* __restrict__ outF0)
{
    __shared__ __align__(16) float smem[NW * WSH];

    const int lane = threadIdx.x & 31;
    const int wrp  = threadIdx.x >> 5;
    const int b    = blockIdx.x * NW + wrp;

    float* Wbuf = smem + wrp * WSH;
    float*  p1  = Wbuf;                              // 3 x 148
    const float4* p1_4 = (const float4*)p1;          // row stride 37 float4
    float*  p2  = Wbuf + 444;                        // 36
    const float4* p2_4 = (const float4*)p2;
    float*  h1  = Wbuf + 480;                        // 20
    const float4* h1_4 = (const float4*)h1;

    const float f4lane = (float)(4 * lane);

    // ---- init: x -> registers; xs[0] = x ----
    float4 a[5];
    {
        const float4* x4 = (const float4*)(x + (size_t)b * D_IN) + lane;
        float4* xs0 = (float4*)(outXS + (size_t)b * D_IN) + lane;
        #pragma unroll
        for (int j = 0; j < 5; ++j) {
            if (j < 4 || lane < 20) {
                a[j] = x4[32 * j];
                __stcs(&xs0[32 * j], a[j]);
            }
        }
    }

    // lane-folded streaming output pointers (advance per bank); store index 32*j -> imm offset
    const size_t ROWSTEP = (size_t)NBATCH * D_IN / 4;
    float4* pH  = (float4*)(outH  + (size_t)b * D_IN) + lane;
    float4* pXF = (float4*)(outXF + (size_t)b * D_IN) + lane;
    float4* pXS = (float4*)(outXS + (size_t)b * D_IN) + lane + ROWSTEP;  // xs row for bank i+1

    #pragma unroll 2
    for (int i = 0; i < FB; ++i) {
        const float* cw = c_cw + i * CPB;

        // ---- conv1 (k=3,s=2,3ch) + maxpool3s2 + relu; neighbor via merged shuffle ----
        {
            #pragma unroll
            for (int j = 0; j < 5; ++j) {
                // need e4,e5,e6 = first 3 floats of float4[t+1]
                float e4, e5, e6;
                if (j < 4) {
                    // lane L<31 takes lane L+1's a[j]; lane31 takes lane0's a[j+1]
                    float vx = (lane == 0) ? a[j + 1].x : a[j].x;
                    float vy = (lane == 0) ? a[j + 1].y : a[j].y;
                    float vz = (lane == 0) ? a[j + 1].z : a[j].z;
                    e4 = __shfl_sync(FULLM, vx, (lane + 1) & 31);
                    e5 = __shfl_sync(FULLM, vy, (lane + 1) & 31);
                    e6 = __shfl_sync(FULLM, vz, (lane + 1) & 31);
                } else {
                    // j=4: active t<147 -> lane<19; neighbor within warp
                    e4 = __shfl_sync(FULLM, a[4].x, (lane + 1) & 31);
                    e5 = __shfl_sync(FULLM, a[4].y, (lane + 1) & 31);
                    e6 = __shfl_sync(FULLM, a[4].z, (lane + 1) & 31);
                }
                int t = lane + 32 * j;
                if (t < 147) {
                    float e0 = a[j].x, e1 = a[j].y, e2 = a[j].z, e3 = a[j].w;
                    #pragma unroll
                    for (int o = 0; o < 3; ++o) {
                        float w0 = cw[o*3], wA = cw[o*3+1], wB = cw[o*3+2], bb = cw[9+o];
                        float c0  = fmaf(e0, w0, fmaf(e1, wA, fmaf(e2, wB, bb)));
                        float c1v = fmaf(e2, w0, fmaf(e3, wA, fmaf(e4, wB, bb)));
                        float c2v = fmaf(e4, w0, fmaf(e5, wA, fmaf(e6, wB, bb)));
                        p1[o * 148 + t] = fmaxf(fmaxf(fmaxf(c0, c1v), c2v), 0.f);
                    }
                }
            }
        }
        __syncwarp();

        // ---- conv2 (3ch->1, k=3,s=2) + maxpool3s2 + relu ----
        {
            float bb = cw[21];
            #pragma unroll
            for (int j = 0; j < 2; ++j) {
                int t = lane + 32 * j;
                if (t < 36) {
                    float c0 = bb, c1v = bb, c2v = bb;
                    #pragma unroll
                    for (int c = 0; c < 3; ++c) {
                        float w0 = cw[12+c*3], wA = cw[12+c*3+1], wB = cw[12+c*3+2];
                        float4 P = p1_4[c * 37 + t];
                        float4 Q = p1_4[c * 37 + t + 1];
                        c0  = fmaf(P.x, w0, fmaf(P.y, wA, fmaf(P.z, wB, c0)));
                        c1v = fmaf(P.z, w0, fmaf(P.w, wA, fmaf(Q.x, wB, c1v)));
                        c2v = fmaf(Q.x, w0, fmaf(Q.y, wA, fmaf(Q.z, wB, c2v)));
                    }
                    p2[t] = fmaxf(fmaxf(fmaxf(c0, c1v), c2v), 0.f);
                }
            }
        }
        __syncwarp();

        // ---- lin1: 36 -> 20, relu (p2 broadcast float4) ----
        if (lane < 20) {
            const float4* w4 = (const float4*)l1w + ((size_t)i * 20 + lane) * 9;
            float acc = l1b[i * 20 + lane], acc2 = 0.f;
            #pragma unroll
            for (int k = 0; k < 9; ++k) {
                float4 wv = w4[k];
                float4 pv = p2_4[k];
                acc  = fmaf(pv.x, wv.x, acc);
                acc2 = fmaf(pv.y, wv.y, acc2);
                acc  = fmaf(pv.z, wv.z, acc);
                acc2 = fmaf(pv.w, wv.w, acc2);
            }
            h1[lane] = fmaxf(acc + acc2, 0.f);
        }
        __syncwarp();

        // ---- lin2: 20 -> 10 relu, lin3: 10 -> 1, sigmoid (h1 broadcast float4) ----
        float v = 0.f;
        if (lane < 10) {
            const float4* wv4 = (const float4*)l2w + ((size_t)i * 10 + lane) * 5;
            float acc = l2b[i * 10 + lane], acc2 = 0.f;
            #pragma unroll
            for (int k = 0; k < 5; ++k) {
                float4 wv = wv4[k];
                float4 hv = h1_4[k];
                acc  = fmaf(hv.x, wv.x, acc);
                acc2 = fmaf(hv.y, wv.y, acc2);
                acc  = fmaf(hv.z, wv.z, acc);
                acc2 = fmaf(hv.w, wv.w, acc2);
            }
            float h2 = fmaxf(acc + acc2, 0.f);
            v = h2 * l3w[i * 10 + lane];
        }
        #pragma unroll
        for (int off = 8; off; off >>= 1)
            v += __shfl_xor_sync(FULLM, v, off);

        float f0 = 0.f;
        if (lane == 0) {
            float z  = v + cw[22];
            float sg = 1.f / (1.f + __expf(-z));
            f0 = (float)D_IN * sg;
            outF0[(size_t)i * NBATCH + b] = f0;
        }
        f0 = __shfl_sync(FULLM, f0, 0);

        // ---- H via Gaussian recurrence: H(d+k) = H(d)*E^k*exp2(k^2 c), E = exp2(2dc) ----
        {
            const float cexp2 = -0.02f * 1.442695041f;     // c = -log2(e)/50
            const float K1 = 0.98019867f;                   // e^-0.02
            const float K4 = 0.92311635f;                   // e^-0.08
            const float K9 = 0.83527021f;                   // e^-0.18
            const float dbase = f4lane - f0;                // per-bank hoist
            if (i < FB - 1) {
                #pragma unroll
                for (int j = 0; j < 5; ++j) {
                    if (j < 4 || lane < 20) {
                        float d0 = dbase + (float)(128 * j);
                        float t0 = d0 * cexp2;
                        float4 H;
                        H.x = exp2f(d0 * t0);
                        float E  = exp2f(t0 + t0);
                        float E2 = E * E;
                        float HE  = H.x * E;
                        float HE2 = H.x * E2;
                        H.y = HE  * K1;
                        H.z = HE2 * K4;
                        H.w = (HE2 * E) * K9;
                        float4 xf = make_float4(a[j].x * H.x, a[j].y * H.y,
                                                a[j].z * H.z, a[j].w * H.w);
                        __stcs(&pH[32 * j],  H);
                        __stcs(&pXF[32 * j], xf);
                        a[j].x -= xf.x; a[j].y -= xf.y;
                        a[j].z -= xf.z; a[j].w -= xf.w;
                        __stcs(&pXS[32 * j], a[j]);
                    }
                }
            } else {
                #pragma unroll
                for (int j = 0; j < 5; ++j) {
                    if (j < 4 || lane < 20) {
                        float d0 = dbase + (float)(128 * j);
                        float t0 = d0 * cexp2;
                        float4 H;
                        H.x = exp2f(d0 * t0);
                        float E  = exp2f(t0 + t0);
                        float E2 = E * E;
                        float HE  = H.x * E;
                        float HE2 = H.x * E2;
                        H.y = HE  * K1;
                        H.z = HE2 * K4;
                        H.w = (HE2 * E) * K9;
                        float4 xf = make_float4(a[j].x * H.x, a[j].y * H.y,
                                                a[j].z * H.z, a[j].w * H.w);
                        __stcs(&pH[32 * j],  H);
                        __stcs(&pXF[32 * j], xf);
                    }
                }
            }
            pH  += ROWSTEP;
            pXF += ROWSTEP;
            pXS += ROWSTEP;
        }
        // no end-of-bank __syncwarp: stream touches no smem; next conv1's p1
        // writes are ordered >=3 syncs after conv2's last p1 reads
    }
}

// pack [conv1_w | conv1_b | conv2_w | conv2_b | lin3_b] per bank into c_cw
__global__ void pack_const_kernel(const float* __restrict__ c1w, const float* __restrict__ c1b,
                                  const float* __restrict__ c2w, const float* __restrict__ c2b,
                                  const float* __restrict__ l3b, float* __restrict__ dst) {
    int i = threadIdx.x;  // bank
    if (i < FB) {
        float* d = dst + i * CPB;
        #pragma unroll
        for (int k = 0; k < 9; ++k) d[k] = c1w[i * 9 + k];
        #pragma unroll
        for (int k = 0; k < 3; ++k) d[9 + k] = c1b[i * 3 + k];
        #pragma unroll
        for (int k = 0; k < 9; ++k) d[12 + k] = c2w[i * 9 + k];
        d[21] = c2b[i];
        d[22] = l3b[i];
    }
}

__device__ float d_cw_stage[FB * CPB];

extern "C" void kernel_launch(void* const* d_in, const int* in_sizes, int n_in,
                              void* d_out, int out_size) {
    const float* x   = (const float*)d_in[0];
    const float* c1w = (const float*)d_in[1];
    const float* c1b = (const float*)d_in[2];
    const float* c2w = (const float*)d_in[3];
    const float* c2b = (const float*)d_in[4];
    const float* l1w = (const float*)d_in[5];
    const float* l1b = (const float*)d_in[6];
    const float* l2w = (const float*)d_in[7];
    const float* l2b = (const float*)d_in[8];
    const float* l3w = (const float*)d_in[9];
    const float* l3b = (const float*)d_in[10];

    // stage packed uniform weights, then copy into constant bank (async D2D)
    void* stage_ptr = nullptr;
    cudaGetSymbolAddress(&stage_ptr, d_cw_stage);
    pack_const_kernel<<<1, 32>>>(c1w, c1b, c2w, c2b, l3b, (float*)stage_ptr);
    cudaMemcpyToSymbolAsync(c_cw, stage_ptr, FB * CPB * sizeof(float), 0,
                            cudaMemcpyDeviceToDevice);

    float* out = (float*)d_out;
    const size_t FBD = (size_t)FB * NBATCH * D_IN;
    float* outH  = out;
    float* outXF = out + FBD;
    float* outXS = out + 2 * FBD;
    float* outF0 = out + 3 * FBD;

    fbank_kernel<<<NBATCH / NW, NT>>>(x, l1w, l1b, l2w, l2b, l3w,
                                      outH, outXF, outXS, outF0);
}

// round 15
// speedup vs baseline: 1.0472x; 1.0472x over previous
#include <cuda_runtime.h>
#include <cuda_bf16.h>

#define D_IN   592
#define NBATCH 8192
#define FB     8
#define NW     4            // warps (samples) per CTA
#define NT     (NW * 32)
#define WSH    512          // floats/warp: p1 444 + p2 36 + h1 20 (+pad)
#define FULLM  0xffffffffu

// Uniform-accessed small weights live in constant memory (LDCU port, off LSU).
// Layout per bank i: [0..8] conv1_w, [9..11] conv1_b, [12..20] conv2_w, [21] conv2_b, [22] lin3_b
#define CPB 23
__constant__ float c_cw[FB * CPB];

__global__ void __launch_bounds__(NT, 8) fbank_kernel(
    const float* __restrict__ x,
    const float* __restrict__ l1w, const float* __restrict__ l1b,
    const float* __restrict__ l2w, const float* __restrict__ l2b,
    const float* __restrict__ l3w,
    float* __restrict__ outH, float* __restrict__ outXF,
    float* __restrict__ outXS, float* __restrict__ outF0)
{
    __shared__ __align__(16) float smem[NW * WSH];

    const int lane = threadIdx.x & 31;
    const int wrp  = threadIdx.x >> 5;
    const int b    = blockIdx.x * NW + wrp;

    float* Wbuf = smem + wrp * WSH;
    float*  p1  = Wbuf;                              // 3 x 148
    const float4* p1_4 = (const float4*)p1;          // row stride 37 float4
    float*  p2  = Wbuf + 444;                        // 36
    const float4* p2_4 = (const float4*)p2;
    float*  h1  = Wbuf + 480;                        // 20
    const float4* h1_4 = (const float4*)h1;

    const float f4lane = (float)(4 * lane);

    // ---- init: x -> registers; xs[0] = x ----
    float4 a[5];
    {
        const float4* x4 = (const float4*)(x + (size_t)b * D_IN) + lane;
        float4* xs0 = (float4*)(outXS + (size_t)b * D_IN) + lane;
        #pragma unroll
        for (int j = 0; j < 5; ++j) {
            if (j < 4 || lane < 20) {
                a[j] = x4[32 * j];
                __stcs(&xs0[32 * j], a[j]);
            }
        }
    }

    // lane-folded streaming output pointers (advance per bank); store index 32*j -> imm offset
    const size_t ROWSTEP = (size_t)NBATCH * D_IN / 4;
    float4* pH  = (float4*)(outH  + (size_t)b * D_IN) + lane;
    float4* pXF = (float4*)(outXF + (size_t)b * D_IN) + lane;
    float4* pXS = (float4*)(outXS + (size_t)b * D_IN) + lane + ROWSTEP;  // xs row for bank i+1

    #pragma unroll 1
    for (int i = 0; i < FB; ++i) {
        const float* cw = c_cw + i * CPB;

        // ---- conv1 (k=3,s=2,3ch) + maxpool3s2 + relu; neighbor via merged shuffle ----
        {
            #pragma unroll
            for (int j = 0; j < 5; ++j) {
                // need e4,e5,e6 = first 3 floats of float4[t+1]
                float e4, e5, e6;
                if (j < 4) {
                    // lane L<31 takes lane L+1's a[j]; lane31 takes lane0's a[j+1]
                    float vx = (lane == 0) ? a[j + 1].x : a[j].x;
                    float vy = (lane == 0) ? a[j + 1].y : a[j].y;
                    float vz = (lane == 0) ? a[j + 1].z : a[j].z;
                    e4 = __shfl_sync(FULLM, vx, (lane + 1) & 31);
                    e5 = __shfl_sync(FULLM, vy, (lane + 1) & 31);
                    e6 = __shfl_sync(FULLM, vz, (lane + 1) & 31);
                } else {
                    // j=4: active t<147 -> lane<19; neighbor within warp
                    e4 = __shfl_sync(FULLM, a[4].x, (lane + 1) & 31);
                    e5 = __shfl_sync(FULLM, a[4].y, (lane + 1) & 31);
                    e6 = __shfl_sync(FULLM, a[4].z, (lane + 1) & 31);
                }
                int t = lane + 32 * j;
                if (t < 147) {
                    float e0 = a[j].x, e1 = a[j].y, e2 = a[j].z, e3 = a[j].w;
                    #pragma unroll
                    for (int o = 0; o < 3; ++o) {
                        float w0 = cw[o*3], wA = cw[o*3+1], wB = cw[o*3+2], bb = cw[9+o];
                        float c0  = fmaf(e0, w0, fmaf(e1, wA, fmaf(e2, wB, bb)));
                        float c1v = fmaf(e2, w0, fmaf(e3, wA, fmaf(e4, wB, bb)));
                        float c2v = fmaf(e4, w0, fmaf(e5, wA, fmaf(e6, wB, bb)));
                        p1[o * 148 + t] = fmaxf(fmaxf(fmaxf(c0, c1v), c2v), 0.f);
                    }
                }
            }
        }
        __syncwarp();

        // ---- conv2 (3ch->1, k=3,s=2) + maxpool3s2 + relu ----
        {
            float bb = cw[21];
            #pragma unroll
            for (int j = 0; j < 2; ++j) {
                int t = lane + 32 * j;
                if (t < 36) {
                    float c0 = bb, c1v = bb, c2v = bb;
                    #pragma unroll
                    for (int c = 0; c < 3; ++c) {
                        float w0 = cw[12+c*3], wA = cw[12+c*3+1], wB = cw[12+c*3+2];
                        float4 P = p1_4[c * 37 + t];
                        float4 Q = p1_4[c * 37 + t + 1];
                        c0  = fmaf(P.x, w0, fmaf(P.y, wA, fmaf(P.z, wB, c0)));
                        c1v = fmaf(P.z, w0, fmaf(P.w, wA, fmaf(Q.x, wB, c1v)));
                        c2v = fmaf(Q.x, w0, fmaf(Q.y, wA, fmaf(Q.z, wB, c2v)));
                    }
                    p2[t] = fmaxf(fmaxf(fmaxf(c0, c1v), c2v), 0.f);
                }
            }
        }
        __syncwarp();

        // ---- lin1: 36 -> 20, relu (p2 broadcast float4) ----
        if (lane < 20) {
            const float4* w4 = (const float4*)l1w + ((size_t)i * 20 + lane) * 9;
            float acc = l1b[i * 20 + lane], acc2 = 0.f;
            #pragma unroll
            for (int k = 0; k < 9; ++k) {
                float4 wv = w4[k];
                float4 pv = p2_4[k];
                acc  = fmaf(pv.x, wv.x, acc);
                acc2 = fmaf(pv.y, wv.y, acc2);
                acc  = fmaf(pv.z, wv.z, acc);
                acc2 = fmaf(pv.w, wv.w, acc2);
            }
            h1[lane] = fmaxf(acc + acc2, 0.f);
        }
        __syncwarp();

        // ---- lin2: 20 -> 10 relu, lin3: 10 -> 1, sigmoid (h1 broadcast float4) ----
        float v = 0.f;
        if (lane < 10) {
            const float4* wv4 = (const float4*)l2w + ((size_t)i * 10 + lane) * 5;
            float acc = l2b[i * 10 + lane], acc2 = 0.f;
            #pragma unroll
            for (int k = 0; k < 5; ++k) {
                float4 wv = wv4[k];
                float4 hv = h1_4[k];
                acc  = fmaf(hv.x, wv.x, acc);
                acc2 = fmaf(hv.y, wv.y, acc2);
                acc  = fmaf(hv.z, wv.z, acc);
                acc2 = fmaf(hv.w, wv.w, acc2);
            }
            float h2 = fmaxf(acc + acc2, 0.f);
            v = h2 * l3w[i * 10 + lane];
        }
        #pragma unroll
        for (int off = 8; off; off >>= 1)
            v += __shfl_xor_sync(FULLM, v, off);

        float f0 = 0.f;
        if (lane == 0) {
            float z  = v + cw[22];
            float sg = 1.f / (1.f + __expf(-z));
            f0 = (float)D_IN * sg;
            outF0[(size_t)i * NBATCH + b] = f0;
        }
        f0 = __shfl_sync(FULLM, f0, 0);

        // ---- H via Gaussian recurrence: H(d+k) = H(d)*E^k*exp2(k^2 c), E = exp2(2dc) ----
        {
            const float cexp2 = -0.02f * 1.442695041f;     // c = -log2(e)/50
            const float K1 = 0.98019867f;                   // e^-0.02
            const float K4 = 0.92311635f;                   // e^-0.08
            const float K9 = 0.83527021f;                   // e^-0.18
            const float dbase = f4lane - f0;                // per-bank hoist
            if (i < FB - 1) {
                #pragma unroll
                for (int j = 0; j < 5; ++j) {
                    if (j < 4 || lane < 20) {
                        float d0 = dbase + (float)(128 * j);
                        float t0 = d0 * cexp2;
                        float4 H;
                        H.x = exp2f(d0 * t0);
                        float E  = exp2f(t0 + t0);
                        float E2 = E * E;
                        float HE  = H.x * E;
                        float HE2 = H.x * E2;
                        H.y = HE  * K1;
                        H.z = HE2 * K4;
                        H.w = (HE2 * E) * K9;
                        float4 xf = make_float4(a[j].x * H.x, a[j].y * H.y,
                                                a[j].z * H.z, a[j].w * H.w);
                        __stcs(&pH[32 * j],  H);
                        __stcs(&pXF[32 * j], xf);
                        a[j].x -= xf.x; a[j].y -= xf.y;
                        a[j].z -= xf.z; a[j].w -= xf.w;
                        __stcs(&pXS[32 * j], a[j]);
                    }
                }
            } else {
                #pragma unroll
                for (int j = 0; j < 5; ++j) {
                    if (j < 4 || lane < 20) {
                        float d0 = dbase + (float)(128 * j);
                        float t0 = d0 * cexp2;
                        float4 H;
                        H.x = exp2f(d0 * t0);
                        float E  = exp2f(t0 + t0);
                        float E2 = E * E;
                        float HE  = H.x * E;
                        float HE2 = H.x * E2;
                        H.y = HE  * K1;
                        H.z = HE2 * K4;
                        H.w = (HE2 * E) * K9;
                        float4 xf = make_float4(a[j].x * H.x, a[j].y * H.y,
                                                a[j].z * H.z, a[j].w * H.w);
                        __stcs(&pH[32 * j],  H);
                        __stcs(&pXF[32 * j], xf);
                    }
                }
            }
            pH  += ROWSTEP;
            pXF += ROWSTEP;
            pXS += ROWSTEP;
        }
        // no end-of-bank __syncwarp: stream phase touches no smem; next conv1's
        // p1 writes are ordered >=3 syncwarps after conv2's last p1 reads
    }
}

// pack [conv1_w | conv1_b | conv2_w | conv2_b | lin3_b] per bank into c_cw
__global__ void pack_const_kernel(const float* __restrict__ c1w, const float* __restrict__ c1b,
                                  const float* __restrict__ c2w, const float* __restrict__ c2b,
                                  const float* __restrict__ l3b, float* __restrict__ dst) {
    int i = threadIdx.x;  // bank
    if (i < FB) {
        float* d = dst + i * CPB;
        #pragma unroll
        for (int k = 0; k < 9; ++k) d[k] = c1w[i * 9 + k];
        #pragma unroll
        for (int k = 0; k < 3; ++k) d[9 + k] = c1b[i * 3 + k];
        #pragma unroll
        for (int k = 0; k < 9; ++k) d[12 + k] = c2w[i * 9 + k];
        d[21] = c2b[i];
        d[22] = l3b[i];
    }
}

__device__ float d_cw_stage[FB * CPB];

extern "C" void kernel_launch(void* const* d_in, const int* in_sizes, int n_in,
                              void* d_out, int out_size) {
    const float* x   = (const float*)d_in[0];
    const float* c1w = (const float*)d_in[1];
    const float* c1b = (const float*)d_in[2];
    const float* c2w = (const float*)d_in[3];
    const float* c2b = (const float*)d_in[4];
    const float* l1w = (const float*)d_in[5];
    const float* l1b = (const float*)d_in[6];
    const float* l2w = (const float*)d_in[7];
    const float* l2b = (const float*)d_in[8];
    const float* l3w = (const float*)d_in[9];
    const float* l3b = (const float*)d_in[10];

    // stage packed uniform weights, then copy into constant bank (async D2D)
    void* stage_ptr = nullptr;
    cudaGetSymbolAddress(&stage_ptr, d_cw_stage);
    pack_const_kernel<<<1, 32>>>(c1w, c1b, c2w, c2b, l3b, (float*)stage_ptr);
    cudaMemcpyToSymbolAsync(c_cw, stage_ptr, FB * CPB * sizeof(float), 0,
                            cudaMemcpyDeviceToDevice);

    float* out = (float*)d_out;
    const size_t FBD = (size_t)FB * NBATCH * D_IN;
    float* outH  = out;
    float* outXF = out + FBD;
    float* outXS = out + 2 * FBD;
    float* outF0 = out + 3 * FBD;

    fbank_kernel<<<NBATCH / NW, NT>>>(x, l1w, l1b, l2w, l2b, l3w,
                                      outH, outXF, outXS, outF0);
}

// round 16
// speedup vs baseline: 1.0484x; 1.0011x over previous
#include <cuda_runtime.h>
#include <cuda_bf16.h>

#define D_IN   592
#define NBATCH 8192
#define FB     8
#define NW     4            // warps (samples) per CTA
#define NT     (NW * 32)
#define WSH    512          // floats/warp: p1 444 + p2 36 + h1 20 (+pad)
#define FULLM  0xffffffffu

// Uniform-accessed small weights live in constant memory (LDCU port, off LSU).
// Layout per bank i: [0..8] conv1_w, [9..11] conv1_b, [12..20] conv2_w, [21] conv2_b, [22] lin3_b
#define CPB 23
__constant__ float c_cw[FB * CPB];

__global__ void __launch_bounds__(NT, 8) fbank_kernel(
    const float* __restrict__ x,
    const float* __restrict__ l1w, const float* __restrict__ l1b,
    const float* __restrict__ l2w, const float* __restrict__ l2b,
    const float* __restrict__ l3w,
    float* __restrict__ outH, float* __restrict__ outXF,
    float* __restrict__ outXS, float* __restrict__ outF0)
{
    __shared__ __align__(16) float smem[NW * WSH];

    const int lane = threadIdx.x & 31;
    const int wrp  = threadIdx.x >> 5;
    const int b    = blockIdx.x * NW + wrp;

    float* Wbuf = smem + wrp * WSH;
    float*  p1  = Wbuf;                              // 3 x 148
    const float4* p1_4 = (const float4*)p1;          // row stride 37 float4
    float*  p2  = Wbuf + 444;                        // 36
    const float4* p2_4 = (const float4*)p2;
    float*  h1  = Wbuf + 480;                        // 20
    const float4* h1_4 = (const float4*)h1;

    const float f4lane = (float)(4 * lane);

    // ---- init: x -> registers; xs[0] = x ----
    float4 a[5];
    {
        const float4* x4 = (const float4*)(x + (size_t)b * D_IN) + lane;
        float4* xs0 = (float4*)(outXS + (size_t)b * D_IN) + lane;
        #pragma unroll
        for (int j = 0; j < 5; ++j) {
            if (j < 4 || lane < 20) {
                a[j] = x4[32 * j];
                __stcs(&xs0[32 * j], a[j]);
            }
        }
    }

    // lane-folded streaming output pointers (advance per bank); store index 32*j -> imm offset
    const size_t ROWSTEP = (size_t)NBATCH * D_IN / 4;
    float4* pH  = (float4*)(outH  + (size_t)b * D_IN) + lane;
    float4* pXF = (float4*)(outXF + (size_t)b * D_IN) + lane;
    float4* pXS = (float4*)(outXS + (size_t)b * D_IN) + lane + ROWSTEP;  // xs row for bank i+1
    float*  pF0 = outF0 + b;                                             // advance by NBATCH

    #pragma unroll 1
    for (int i = 0; i < FB; ++i) {
        const float* cw = c_cw + i * CPB;

        // ---- conv1 (k=3,s=2,3ch) + maxpool3s2 + relu; neighbor via merged shuffle ----
        {
            #pragma unroll
            for (int j = 0; j < 5; ++j) {
                // need e4,e5,e6 = first 3 floats of float4[t+1]
                float e4, e5, e6;
                if (j < 4) {
                    // lane L<31 takes lane L+1's a[j]; lane31 takes lane0's a[j+1]
                    float vx = (lane == 0) ? a[j + 1].x : a[j].x;
                    float vy = (lane == 0) ? a[j + 1].y : a[j].y;
                    float vz = (lane == 0) ? a[j + 1].z : a[j].z;
                    e4 = __shfl_sync(FULLM, vx, (lane + 1) & 31);
                    e5 = __shfl_sync(FULLM, vy, (lane + 1) & 31);
                    e6 = __shfl_sync(FULLM, vz, (lane + 1) & 31);
                } else {
                    // j=4: active t<147 -> lane<19; neighbor within warp
                    e4 = __shfl_sync(FULLM, a[4].x, (lane + 1) & 31);
                    e5 = __shfl_sync(FULLM, a[4].y, (lane + 1) & 31);
                    e6 = __shfl_sync(FULLM, a[4].z, (lane + 1) & 31);
                }
                int t = lane + 32 * j;
                if (t < 147) {
                    float e0 = a[j].x, e1 = a[j].y, e2 = a[j].z, e3 = a[j].w;
                    #pragma unroll
                    for (int o = 0; o < 3; ++o) {
                        float w0 = cw[o*3], wA = cw[o*3+1], wB = cw[o*3+2], bb = cw[9+o];
                        float c0  = fmaf(e0, w0, fmaf(e1, wA, fmaf(e2, wB, bb)));
                        float c1v = fmaf(e2, w0, fmaf(e3, wA, fmaf(e4, wB, bb)));
                        float c2v = fmaf(e4, w0, fmaf(e5, wA, fmaf(e6, wB, bb)));
                        p1[o * 148 + t] = fmaxf(fmaxf(fmaxf(c0, c1v), c2v), 0.f);
                    }
                }
            }
        }
        __syncwarp();

        // ---- conv2 (3ch->1, k=3,s=2) + maxpool3s2 + relu ----
        {
            float bb = cw[21];
            #pragma unroll
            for (int j = 0; j < 2; ++j) {
                int t = lane + 32 * j;
                if (t < 36) {
                    float c0 = bb, c1v = bb, c2v = bb;
                    #pragma unroll
                    for (int c = 0; c < 3; ++c) {
                        float w0 = cw[12+c*3], wA = cw[12+c*3+1], wB = cw[12+c*3+2];
                        float4 P = p1_4[c * 37 + t];
                        float4 Q = p1_4[c * 37 + t + 1];
                        c0  = fmaf(P.x, w0, fmaf(P.y, wA, fmaf(P.z, wB, c0)));
                        c1v = fmaf(P.z, w0, fmaf(P.w, wA, fmaf(Q.x, wB, c1v)));
                        c2v = fmaf(Q.x, w0, fmaf(Q.y, wA, fmaf(Q.z, wB, c2v)));
                    }
                    p2[t] = fmaxf(fmaxf(fmaxf(c0, c1v), c2v), 0.f);
                }
            }
        }
        __syncwarp();

        // ---- lin1: 36 -> 20, relu (p2 broadcast float4) ----
        if (lane < 20) {
            const float4* w4 = (const float4*)l1w + ((size_t)i * 20 + lane) * 9;
            float acc = l1b[i * 20 + lane], acc2 = 0.f;
            #pragma unroll
            for (int k = 0; k < 9; ++k) {
                float4 wv = w4[k];
                float4 pv = p2_4[k];
                acc  = fmaf(pv.x, wv.x, acc);
                acc2 = fmaf(pv.y, wv.y, acc2);
                acc  = fmaf(pv.z, wv.z, acc);
                acc2 = fmaf(pv.w, wv.w, acc2);
            }
            h1[lane] = fmaxf(acc + acc2, 0.f);
        }
        __syncwarp();

        // ---- lin2: 20 -> 10 relu, lin3: 10 -> 1, sigmoid (h1 broadcast float4) ----
        float v = 0.f;
        if (lane < 10) {
            const float4* wv4 = (const float4*)l2w + ((size_t)i * 10 + lane) * 5;
            float acc = l2b[i * 10 + lane], acc2 = 0.f;
            #pragma unroll
            for (int k = 0; k < 5; ++k) {
                float4 wv = wv4[k];
                float4 hv = h1_4[k];
                acc  = fmaf(hv.x, wv.x, acc);
                acc2 = fmaf(hv.y, wv.y, acc2);
                acc  = fmaf(hv.z, wv.z, acc);
                acc2 = fmaf(hv.w, wv.w, acc2);
            }
            float h2 = fmaxf(acc + acc2, 0.f);
            v = h2 * l3w[i * 10 + lane];
        }
        #pragma unroll
        for (int off = 8; off; off >>= 1)
            v += __shfl_xor_sync(FULLM, v, off);

        float f0 = 0.f;
        if (lane == 0) {
            float z  = v + cw[22];
            float sg = 1.f / (1.f + __expf(-z));
            f0 = (float)D_IN * sg;
            *pF0 = f0;
        }
        f0 = __shfl_sync(FULLM, f0, 0);
        pF0 += NBATCH;

        // ---- H via Gaussian recurrence: H(d+k) = H(d)*E^k*exp2(k^2 c), E = exp2(2dc) ----
        {
            const float cexp2 = -0.02f * 1.442695041f;     // c = -log2(e)/50
            const float K1 = 0.98019867f;                   // e^-0.02
            const float K4 = 0.92311635f;                   // e^-0.08
            const float K9 = 0.83527021f;                   // e^-0.18
            const float dbase = f4lane - f0;                // per-bank hoist
            if (i < FB - 1) {
                #pragma unroll
                for (int j = 0; j < 5; ++j) {
                    if (j < 4 || lane < 20) {
                        float d0 = dbase + (float)(128 * j);
                        float t0 = d0 * cexp2;
                        float4 H;
                        H.x = exp2f(d0 * t0);
                        float E  = exp2f(t0 + t0);
                        float E2 = E * E;
                        float HE  = H.x * E;
                        float HE2 = H.x * E2;
                        H.y = HE  * K1;
                        H.z = HE2 * K4;
                        H.w = (HE2 * E) * K9;
                        float4 xf = make_float4(a[j].x * H.x, a[j].y * H.y,
                                                a[j].z * H.z, a[j].w * H.w);
                        __stcs(&pH[32 * j],  H);
                        __stcs(&pXF[32 * j], xf);
                        a[j].x -= xf.x; a[j].y -= xf.y;
                        a[j].z -= xf.z; a[j].w -= xf.w;
                        __stcs(&pXS[32 * j], a[j]);
                    }
                }
            } else {
                #pragma unroll
                for (int j = 0; j < 5; ++j) {
                    if (j < 4 || lane < 20) {
                        float d0 = dbase + (float)(128 * j);
                        float t0 = d0 * cexp2;
                        float4 H;
                        H.x = exp2f(d0 * t0);
                        float E  = exp2f(t0 + t0);
                        float E2 = E * E;
                        float HE  = H.x * E;
                        float HE2 = H.x * E2;
                        H.y = HE  * K1;
                        H.z = HE2 * K4;
                        H.w = (HE2 * E) * K9;
                        float4 xf = make_float4(a[j].x * H.x, a[j].y * H.y,
                                                a[j].z * H.z, a[j].w * H.w);
                        __stcs(&pH[32 * j],  H);
                        __stcs(&pXF[32 * j], xf);
                    }
                }
            }
            pH  += ROWSTEP;
            pXF += ROWSTEP;
            pXS += ROWSTEP;
        }
        // no end-of-bank __syncwarp: stream phase touches no smem; next conv1's
        // p1 writes are ordered >=3 syncwarps after conv2's last p1 reads
    }
}

// pack [conv1_w | conv1_b | conv2_w | conv2_b | lin3_b] per bank into c_cw
__global__ void pack_const_kernel(const float* __restrict__ c1w, const float* __restrict__ c1b,
                                  const float* __restrict__ c2w, const float* __restrict__ c2b,
                                  const float* __restrict__ l3b, float* __restrict__ dst) {
    int i = threadIdx.x;  // bank
    if (i < FB) {
        float* d = dst + i * CPB;
        #pragma unroll
        for (int k = 0; k < 9; ++k) d[k] = c1w[i * 9 + k];
        #pragma unroll
        for (int k = 0; k < 3; ++k) d[9 + k] = c1b[i * 3 + k];
        #pragma unroll
        for (int k = 0; k < 9; ++k) d[12 + k] = c2w[i * 9 + k];
        d[21] = c2b[i];
        d[22] = l3b[i];
    }
}

__device__ float d_cw_stage[FB * CPB];

extern "C" void kernel_launch(void* const* d_in, const int* in_sizes, int n_in,
                              void* d_out, int out_size) {
    const float* x   = (const float*)d_in[0];
    const float* c1w = (const float*)d_in[1];
    const float* c1b = (const float*)d_in[2];
    const float* c2w = (const float*)d_in[3];
    const float* c2b = (const float*)d_in[4];
    const float* l1w = (const float*)d_in[5];
    const float* l1b = (const float*)d_in[6];
    const float* l2w = (const float*)d_in[7];
    const float* l2b = (const float*)d_in[8];
    const float* l3w = (const float*)d_in[9];
    const float* l3b = (const float*)d_in[10];

    // stage packed uniform weights, then copy into constant bank (async D2D)
    void* stage_ptr = nullptr;
    cudaGetSymbolAddress(&stage_ptr, d_cw_stage);
    pack_const_kernel<<<1, 32>>>(c1w, c1b, c2w, c2b, l3b, (float*)stage_ptr);
    cudaMemcpyToSymbolAsync(c_cw, stage_ptr, FB * CPB * sizeof(float), 0,
                            cudaMemcpyDeviceToDevice);

    float* out = (float*)d_out;
    const size_t FBD = (size_t)FB * NBATCH * D_IN;
    float* outH  = out;
    float* outXF = out + FBD;
    float* outXS = out + 2 * FBD;
    float* outF0 = out + 3 * FBD;

    fbank_kernel<<<NBATCH / NW, NT>>>(x, l1w, l1b, l2w, l2b, l3w,
                                      outH, outXF, outXS, outF0);
}